// round 7
// baseline (speedup 1.0000x reference)
#include <cuda_runtime.h>
#include <cstdint>

// ItemEncoder R7: TMA-bulk gather pipeline + ping-pong consumer groups.
//   out[t,:] = M[ids[t],:] @ W^T + b ; 12800 tokens, D=2000, O=8.
//
//  - 1 CTA / SM, 544 threads = 17 warps:
//      warps 0-7  : consumer group 0 (stages k%2==0, ring slots {0,2,4})
//      warps 8-15 : consumer group 1 (stages k%2==1, ring slots {1,3,5})
//      warp  16   : producer (lane 0 issues cp.async.bulk rows)
//  - 6-slot x 32000 B smem ring; producer keeps up to 192 KB in flight.
//  - Consumers: W via __ldg (L1-resident, 64 KB), ZEROED for quads >= 500
//    (out-of-range v reads hit neighbor-token data / pad; W=0 masks them —
//    this was the R6 bug: clamping W instead of zeroing it).
//  - Packed fp32x2 FMAs, butterfly transpose-reduce, per-group named
//    barrier + red area, one coalesced 128 B store per stage.

static constexpr int NTOK  = 12800;
static constexpr int D     = 2000;
static constexpr int ROWB  = D * 4;          // 8000 B
static constexpr int QPR   = D / 4;          // 500
static constexpr int STOK  = 4;
static constexpr int NSTG  = NTOK / STOK;    // 3200
static constexpr int NTHR  = 544;
static constexpr int NGRP  = 256;            // threads per consumer group
static constexpr int NBUF  = 6;
static constexpr int STAGEB  = STOK * ROWB;  // 32000
static constexpr int BSTRIDE = 32256;        // + 256 B zeroed pad (t=3 quads 500..511)
static constexpr int SM_RED  = NBUF * BSTRIDE;        // 193536 (2 groups x 1024 B)
static constexpr int SM_MBAR = SM_RED + 2048;
static constexpr int SM_TOT  = SM_MBAR + NBUF * 16;

__device__ __forceinline__ void ffma2(unsigned long long &acc,
                                      unsigned long long a,
                                      unsigned long long b) {
    asm("fma.rn.f32x2 %0, %1, %2, %0;" : "+l"(acc) : "l"(a), "l"(b));
}
__device__ __forceinline__ void mbar_init(uint32_t a, uint32_t cnt) {
    asm volatile("mbarrier.init.shared.b64 [%0], %1;" :: "r"(a), "r"(cnt) : "memory");
}
__device__ __forceinline__ void mbar_expect_tx(uint32_t a, uint32_t bytes) {
    asm volatile("mbarrier.arrive.expect_tx.shared.b64 _, [%0], %1;"
                 :: "r"(a), "r"(bytes) : "memory");
}
__device__ __forceinline__ void mbar_arrive(uint32_t a) {
    asm volatile("mbarrier.arrive.shared.b64 _, [%0];" :: "r"(a) : "memory");
}
__device__ __forceinline__ void mbar_wait(uint32_t a, uint32_t parity) {
    asm volatile(
        "{\n\t.reg .pred P;\n\t"
        "WL_%=:\n\t"
        "mbarrier.try_wait.parity.acquire.cta.shared::cta.b64 P, [%0], %1, 0x989680;\n\t"
        "@P bra WD_%=;\n\t"
        "bra WL_%=;\n\t"
        "WD_%=:\n\t}"
        :: "r"(a), "r"(parity) : "memory");
}
__device__ __forceinline__ void bulk_cp(uint32_t smem_dst, const void* gmem_src,
                                        uint32_t bytes, uint32_t mbar) {
    asm volatile(
        "cp.async.bulk.shared::cta.global.mbarrier::complete_tx::bytes "
        "[%0], [%1], %2, [%3];"
        :: "r"(smem_dst), "l"(gmem_src), "r"(bytes), "r"(mbar) : "memory");
}
__device__ __forceinline__ void bar_grp(int barid) {   // 256-thread group barrier
    asm volatile("bar.sync %0, %1;" :: "r"(barid), "n"(NGRP) : "memory");
}

__global__ void __launch_bounds__(NTHR, 1)
gather_proj_r7(const int*   __restrict__ ids,
               const float* __restrict__ M,
               const float* __restrict__ W,
               const float* __restrict__ bias,
               float*       __restrict__ out)
{
    extern __shared__ char smem[];
    const uint32_t smem_u32 = (uint32_t)__cvta_generic_to_shared(smem);
    const int tid  = threadIdx.x;
    const int lane = tid & 31;
    const int wid  = tid >> 5;

    const int gridn  = gridDim.x;
    const int s0     = blockIdx.x;
    const int nLocal = (NSTG - s0 + gridn - 1) / gridn;

    auto fullb  = [&](int s) -> uint32_t { return smem_u32 + SM_MBAR + s * 16; };
    auto emptyb = [&](int s) -> uint32_t { return smem_u32 + SM_MBAR + s * 16 + 8; };

    // ---- init ----
    if (tid == 0) {
#pragma unroll
        for (int s = 0; s < NBUF; ++s) {
            mbar_init(fullb(s), 1);        // armed by producer expect_tx
            mbar_init(emptyb(s), NGRP);    // owning group's 256 threads arrive
        }
    }
    if (tid < NBUF * 16) {                 // zero 6 x 256 B pads
        int b = tid >> 4, q = tid & 15;
        *(float4*)(smem + b * BSTRIDE + STAGEB + q * 16) =
            make_float4(0.f, 0.f, 0.f, 0.f);
    }
    __syncthreads();

    if (wid == 16) {
        // ================= producer =================
        if (lane == 0) {
            const char* Mb = (const char*)M;
            int phase = 1;                 // fresh barriers: first waits pass
            for (int k = 0; k < nLocal; ++k) {
                const int slot = k % NBUF;
                mbar_wait(emptyb(slot), phase);
                const int4 ii = __ldg((const int4*)ids + (s0 + k * gridn));
                const uint32_t dst = smem_u32 + slot * BSTRIDE;
                mbar_expect_tx(fullb(slot), STAGEB);
                bulk_cp(dst,            Mb + (size_t)ii.x * ROWB, ROWB, fullb(slot));
                bulk_cp(dst + ROWB,     Mb + (size_t)ii.y * ROWB, ROWB, fullb(slot));
                bulk_cp(dst + 2 * ROWB, Mb + (size_t)ii.z * ROWB, ROWB, fullb(slot));
                bulk_cp(dst + 3 * ROWB, Mb + (size_t)ii.w * ROWB, ROWB, fullb(slot));
                if (slot == NBUF - 1) phase ^= 1;
            }
        }
        return;
    }

    // ================= consumers =================
    const int g  = wid >> 3;     // group 0 / 1
    const int ww = wid & 7;      // warp within group: owns quads [ww*64, ww*64+64)
    const float bval = __ldg(bias + (lane & 7));
    const ulonglong2* Wq = (const ulonglong2*)W;
    float* red = (float*)(smem + SM_RED) + g * 256;

    int phase = 0, scyc = 0;     // each group's slot set cycles with period 3

    for (int k = g; k < nLocal; k += 2) {
        const int slot = k % NBUF;
        mbar_wait(fullb(slot), phase);
        const char* buf = smem + slot * BSTRIDE;

        unsigned long long acc[4][8];
#pragma unroll
        for (int t = 0; t < 4; ++t)
#pragma unroll
            for (int o = 0; o < 8; ++o) acc[t][o] = 0ull;

#pragma unroll
        for (int it = 0; it < 2; ++it) {
            const int  q   = ww * 64 + it * 32 + lane;  // may be 500..511
            const bool inb = (q < QPR);
            ulonglong2 v[4];
#pragma unroll
            for (int t = 0; t < 4; ++t)
                v[t] = *(const ulonglong2*)(buf + t * ROWB + q * 16);
#pragma unroll
            for (int o = 0; o < 8; ++o) {
                // W ZEROED out of range: stray v (neighbor-token data) * 0 = 0
                ulonglong2 wv = inb ? __ldg(Wq + o * QPR + q)
                                    : make_ulonglong2(0ull, 0ull);
#pragma unroll
                for (int t = 0; t < 4; ++t) {
                    ffma2(acc[t][o], v[t].x, wv.x);
                    ffma2(acc[t][o], v[t].y, wv.y);
                }
            }
        }
        mbar_arrive(emptyb(slot));           // done reading buf
        if (++scyc == 3) { scyc = 0; phase ^= 1; }

        // collapse f32x2 halves -> 32 scalars, butterfly transpose-reduce
        float cur[32];
#pragma unroll
        for (int t = 0; t < 4; ++t)
#pragma unroll
            for (int o = 0; o < 8; ++o) {
                const unsigned long long a = acc[t][o];
                cur[t * 8 + o] = __uint_as_float((unsigned)a) +
                                 __uint_as_float((unsigned)(a >> 32));
            }
#pragma unroll
        for (int off = 16; off >= 1; off >>= 1) {
            const bool up = (lane & off) != 0;
#pragma unroll
            for (int j = 0; j < off; ++j) {
                float keep = up ? cur[j + off] : cur[j];
                float give = up ? cur[j] : cur[j + off];
                keep += __shfl_xor_sync(0xffffffffu, give, off);
                cur[j] = keep;
            }
        }
        // lane holds partial of output value `lane` (token lane>>3, out lane&7)
        bar_grp(1 + g);                      // (A) prev red reads in this group done
        red[ww * 32 + lane] = cur[0];
        bar_grp(1 + g);                      // (B) red visible within group
        if (ww == 0) {
            float s = bval;
#pragma unroll
            for (int w8 = 0; w8 < 8; ++w8) s += red[w8 * 32 + lane];
            out[(size_t)(s0 + k * gridn) * 32 + lane] = s;
        }
    }
}

extern "C" void kernel_launch(void* const* d_in, const int* in_sizes, int n_in,
                              void* d_out, int out_size) {
    const int*   ids  = (const int*)  d_in[0];
    const float* M    = (const float*)d_in[1];
    const float* W    = (const float*)d_in[2];
    const float* bias = (const float*)d_in[3];
    float*       out  = (float*)d_out;

    cudaFuncSetAttribute(gather_proj_r7,
                         cudaFuncAttributeMaxDynamicSharedMemorySize, SM_TOT);

    int nsm = 148;
    cudaDeviceGetAttribute(&nsm, cudaDevAttrMultiProcessorCount, 0);

    gather_proj_r7<<<nsm, NTHR, SM_TOT>>>(ids, M, W, bias, out);
}